// round 7
// baseline (speedup 1.0000x reference)
#include <cuda_runtime.h>
#include <cstdint>

#define BS      512
#define DIM     128
#define POS_K   32
#define NUM_NEG 1024
#define NEG_PER_BLK 256
#define INV_TEMP (1.0f / 0.07f)

#define D_ST    4                         // pipeline depth (stages in ring)
#define NEG_ST  16                        // negatives per stage (block-wide)
#define STAGE_B (NEG_ST * 2 * 512)        // 16 KB per stage
#define N_STAGE 16                        // stages per item

// Output layout (flattened tuple, float32):
#define O0 0          // inst_v2a_pos [512,1]
#define O1 512        // inst_v2a_neg [512,1024]
#define O2 524800     // inst_a2v_pos [512,1]
#define O3 525312     // inst_a2v_neg [512,1024]
#define O4 1049600    // pos_v2v_pos  [512,32]
#define O5 1065984    // pos_v2v_neg  [512,1024]
#define O6 1590272    // pos_a2a_pos  [512,32]
#define O7 1606656    // pos_a2a_neg  [512,1024]

#define FULL 0xffffffffu

__device__ __forceinline__ float warp_sum(float x) {
#pragma unroll
    for (int o = 16; o; o >>= 1) x += __shfl_xor_sync(FULL, x, o);
    return x;
}

__device__ __forceinline__ float dot4(float4 x, float4 y) {
    return x.x * y.x + x.y * y.y + x.z * y.z + x.w * y.w;
}

__device__ __forceinline__ void grp8_sum2(float& a, float& b) {
#pragma unroll
    for (int o = 4; o; o >>= 1) {
        a += __shfl_xor_sync(FULL, a, o);
        b += __shfl_xor_sync(FULL, b, o);
    }
}

__device__ __forceinline__ void cp_async16(uint32_t dst_smem, const void* src) {
    asm volatile("cp.async.cg.shared.global [%0], [%1], 16;\n"
                 :: "r"(dst_smem), "l"(src) : "memory");
}
__device__ __forceinline__ void cp_commit() {
    asm volatile("cp.async.commit_group;\n" ::: "memory");
}
template <int N>
__device__ __forceinline__ void cp_wait() {
    asm volatile("cp.async.wait_group %0;\n" :: "n"(N) : "memory");
}

// full-warp bitonic sort of one u32 key per lane, ascending across lanes 0..31
__device__ __forceinline__ uint32_t warp_bitonic32(uint32_t key, int lane) {
#pragma unroll
    for (int k = 2; k <= 32; k <<= 1) {
#pragma unroll
        for (int j = k >> 1; j > 0; j >>= 1) {
            uint32_t o = __shfl_xor_sync(FULL, key, j);
            const bool up    = ((lane & k) == 0);
            const bool lower = ((lane & j) == 0);
            const uint32_t mn = min(key, o), mx = max(key, o);
            key = (up == lower) ? mn : mx;
        }
    }
    return key;
}

__global__ __launch_bounds__(256, 3)
void avid_cma_kernel(const float* __restrict__ video,
                     const float* __restrict__ audio,
                     const float4* __restrict__ m1,
                     const float4* __restrict__ m2,
                     const int* __restrict__ y,
                     const int* __restrict__ pos_idx,
                     const int* __restrict__ neg_idx,
                     float* __restrict__ out)
{
    extern __shared__ char ring[];            // D_ST * STAGE_B = 64 KB
    __shared__ float4 sv[32];
    __shared__ float4 sa[32];
    __shared__ float  sout[4][NEG_PER_BLK];   // O1,O3,O5,O7 staging

    const int b    = blockIdx.x;
    const int q    = blockIdx.y;
    const int tid  = threadIdx.x;
    const int lane = tid & 31;
    const int w    = tid >> 5;          // 8 warps
    const int c    = lane & 7;          // chunk within row (c, c+8, c+16, c+24)
    const int r    = lane >> 3;         // 8-lane group id in warp

    // --- load this warp's 32 negative indices and SORT ascending by index ---
    // key = (idx << 5) | j   (idx < 500000 < 2^19, so key fits in 24 bits)
    uint32_t key;
    {
        const uint32_t raw = (uint32_t)__ldg(
            neg_idx + (size_t)b * NUM_NEG + q * NEG_PER_BLK + w * 32 + lane);
        key = (raw << 5) | (uint32_t)lane;
        key = warp_bitonic32(key, lane);
    }
    const uint32_t idxs = key >> 5;     // sorted row index (this lane = rank `lane`)
    const uint32_t jjs  = key & 31;     // original j within warp's slice

    // --- normalize fresh embeddings ---
    if (w == 0) {
        float4 x = reinterpret_cast<const float4*>(video)[b * 32 + lane];
        float ss = warp_sum(dot4(x, x));
        float inv = 1.0f / fmaxf(sqrtf(ss), 1e-12f);
        sv[lane] = make_float4(x.x * inv, x.y * inv, x.z * inv, x.w * inv);
    } else if (w == 1) {
        float4 x = reinterpret_cast<const float4*>(audio)[b * 32 + lane];
        float ss = warp_sum(dot4(x, x));
        float inv = 1.0f / fmaxf(sqrtf(ss), 1e-12f);
        sa[lane] = make_float4(x.x * inv, x.y * inv, x.z * inv, x.w * inv);
    }
    __syncthreads();   // sv/sa visible to all warps

    const float4 v0 = sv[c], v1 = sv[c + 8], v2 = sv[c + 16], v3 = sv[c + 24];
    const float4 a0 = sa[c], a1 = sa[c + 8], a2 = sa[c + 16], a3 = sa[c + 24];

    // --- prologue: issue first D_ST-1 stages (warp-local; sorted order) ---
#pragma unroll
    for (int s = 0; s < D_ST - 1; ++s) {
#pragma unroll
        for (int i = 0; i < 4; ++i) {
            const int t  = w * 4 + i;                   // row slot (warp-owned)
            const int ni = __shfl_sync(FULL, idxs, 2 * s + (i >> 1));
            const float4* src = ((i & 1) ? m2 : m1) + (size_t)ni * 32 + lane;
            uint32_t dst = (uint32_t)__cvta_generic_to_shared(
                ring + (size_t)s * STAGE_B + (size_t)t * 512 + lane * 16);
            cp_async16(dst, src);
        }
        cp_commit();
    }

    // --- pos + self dots (q==0 only), plain LDG while pipeline fills ---
    if (q == 0) {
        const int j  = w * 4 + r;
        const int pi = __ldg(pos_idx + (size_t)b * POS_K + j);
        const float4* p1 = m1 + (size_t)pi * 32 + c;
        const float4* p2 = m2 + (size_t)pi * 32 + c;
        float dvv = dot4(p1[0], v0) + dot4(p1[8], v1) + dot4(p1[16], v2) + dot4(p1[24], v3);
        float daa = dot4(p2[0], a0) + dot4(p2[8], a1) + dot4(p2[16], a2) + dot4(p2[24], a3);
        grp8_sum2(dvv, daa);
        if (c == 0) {
            out[O4 + (size_t)b * POS_K + j] = dvv * INV_TEMP;
            out[O6 + (size_t)b * POS_K + j] = daa * INV_TEMP;
        }
        if (w == 0 && r < 2) {
            const int yi = __ldg(y + b);
            const float4* p = (r == 0 ? m1 : m2) + (size_t)yi * 32 + c;
            float d;
            if (r == 0) d = dot4(p[0], a0) + dot4(p[8], a1) + dot4(p[16], a2) + dot4(p[24], a3);
            else        d = dot4(p[0], v0) + dot4(p[8], v1) + dot4(p[16], v2) + dot4(p[24], v3);
#pragma unroll
            for (int o = 4; o; o >>= 1) d += __shfl_xor_sync(0x0000ffffu, d, o);
            if (c == 0) {
                if (r == 0) out[O2 + b] = d * INV_TEMP;  // inst_a2v_pos
                else        out[O0 + b] = d * INV_TEMP;  // inst_v2a_pos
            }
        }
    }

    // --- main pipeline: per-warp decoupled, ascending-index order ---
    const int t = w * 4 + r;                    // this group's row slot (fixed)
    for (int s = 0; s < N_STAGE; ++s) {
        cp_wait<D_ST - 2>();                    // this warp's stage-s copies done
        __syncwarp();

        // issue stage s + D_ST - 1 (that ring slot is free for this warp)
        const int sn = s + D_ST - 1;
        if (sn < N_STAGE) {
#pragma unroll
            for (int i = 0; i < 4; ++i) {
                const int tt = w * 4 + i;
                const int ni = __shfl_sync(FULL, idxs, 2 * sn + (i >> 1));
                const float4* src = ((i & 1) ? m2 : m1) + (size_t)ni * 32 + lane;
                uint32_t dst = (uint32_t)__cvta_generic_to_shared(
                    ring + (size_t)(sn % D_ST) * STAGE_B + (size_t)tt * 512 + lane * 16);
                cp_async16(dst, src);
            }
        }
        cp_commit();                            // always commit (keeps group count)

        // compute: group handles row slot t = sorted entry 2s+(r>>1), bank r&1
        const float4* buf = reinterpret_cast<const float4*>(
            ring + (size_t)(s % D_ST) * STAGE_B) + (size_t)t * 32;
        const float4 x0 = buf[c], x1 = buf[c + 8], x2 = buf[c + 16], x3 = buf[c + 24];
        float dv = dot4(x0, v0) + dot4(x1, v1) + dot4(x2, v2) + dot4(x3, v3);
        float da = dot4(x0, a0) + dot4(x1, a1) + dot4(x2, a2) + dot4(x3, a3);
        grp8_sum2(dv, da);

        const int jje = __shfl_sync(FULL, jjs, 2 * s + (r >> 1));  // original j
        if (c == 0) {
            const int j = w * 32 + jje;               // position within block's 256
            if ((r & 1) == 0) {                       // m1 row: ·a -> O3, ·v -> O5
                sout[1][j] = da * INV_TEMP;
                sout[2][j] = dv * INV_TEMP;
            } else {                                  // m2 row: ·v -> O1, ·a -> O7
                sout[0][j] = dv * INV_TEMP;
                sout[3][j] = da * INV_TEMP;
            }
        }
    }

    // --- coalesced output flush ---
    __syncthreads();
    const size_t o = (size_t)b * NUM_NEG + (size_t)q * NEG_PER_BLK + tid;
    out[O1 + o] = sout[0][tid];
    out[O3 + o] = sout[1][tid];
    out[O5 + o] = sout[2][tid];
    out[O7 + o] = sout[3][tid];
}

extern "C" void kernel_launch(void* const* d_in, const int* in_sizes, int n_in,
                              void* d_out, int out_size)
{
    const float* video = (const float*)d_in[0];
    const float* audio = (const float*)d_in[1];
    const float4* m1   = (const float4*)d_in[2];
    const float4* m2   = (const float4*)d_in[3];
    const int* y       = (const int*)d_in[4];
    const int* pos_idx = (const int*)d_in[5];
    const int* neg_idx = (const int*)d_in[6];
    float* out         = (float*)d_out;

    const int dyn_smem = D_ST * STAGE_B;   // 64 KB
    cudaFuncSetAttribute(avid_cma_kernel,
                         cudaFuncAttributeMaxDynamicSharedMemorySize, dyn_smem);

    dim3 grid(BS, NUM_NEG / NEG_PER_BLK);  // 512 x 4
    avid_cma_kernel<<<grid, 256, dyn_smem>>>(video, audio, m1, m2, y,
                                             pos_idx, neg_idx, out);
}

// round 8
// speedup vs baseline: 1.0653x; 1.0653x over previous
#include <cuda_runtime.h>
#include <cstdint>

#define BS      512
#define DIM     128
#define POS_K   32
#define NUM_NEG 1024
#define INV_TEMP (1.0f / 0.07f)

#define NBLK    256                       // one fully-resident wave (2/SM)
#define D_ST    4                         // per-warp ring depth
#define N_ST    64                        // stages per sweep (16 negs/stage)
// per warp-stage: 2 negs * 2 banks = 4 rows * 512B = 2 KB; warp ring 8 KB; block ring 64 KB

// Output layout (flattened tuple, float32):
#define O0 0          // inst_v2a_pos [512,1]
#define O1 512        // inst_v2a_neg [512,1024]
#define O2 524800     // inst_a2v_pos [512,1]
#define O3 525312     // inst_a2v_neg [512,1024]
#define O4 1049600    // pos_v2v_pos  [512,32]
#define O5 1065984    // pos_v2v_neg  [512,1024]
#define O6 1590272    // pos_a2a_pos  [512,32]
#define O7 1606656    // pos_a2a_neg  [512,1024]

#define FULL 0xffffffffu

__device__ __forceinline__ float warp_sum(float x) {
#pragma unroll
    for (int o = 16; o; o >>= 1) x += __shfl_xor_sync(FULL, x, o);
    return x;
}

__device__ __forceinline__ float dot4(float4 x, float4 y) {
    return x.x * y.x + x.y * y.y + x.z * y.z + x.w * y.w;
}

__device__ __forceinline__ void grp8_sum2(float& a, float& b) {
#pragma unroll
    for (int o = 4; o; o >>= 1) {
        a += __shfl_xor_sync(FULL, a, o);
        b += __shfl_xor_sync(FULL, b, o);
    }
}

__device__ __forceinline__ void cp_async16(uint32_t dst_smem, const void* src) {
    asm volatile("cp.async.cg.shared.global [%0], [%1], 16;\n"
                 :: "r"(dst_smem), "l"(src) : "memory");
}
__device__ __forceinline__ void cp_commit() {
    asm volatile("cp.async.commit_group;\n" ::: "memory");
}
template <int N>
__device__ __forceinline__ void cp_wait() {
    asm volatile("cp.async.wait_group %0;\n" :: "n"(N) : "memory");
}

__global__ __launch_bounds__(256, 2)
void avid_cma_kernel(const float* __restrict__ video,
                     const float* __restrict__ audio,
                     const float4* __restrict__ m1,
                     const float4* __restrict__ m2,
                     const int* __restrict__ y,
                     const int* __restrict__ pos_idx,
                     const int* __restrict__ neg_idx,
                     float* __restrict__ out)
{
    extern __shared__ char ring[];                 // 8 warps * D_ST * 2048 = 64 KB
    __shared__ uint32_t kbuf[NUM_NEG];             // raw keys (row<<10 | j)
    __shared__ uint32_t sorted[NUM_NEG];           // bucket-sorted keys
    __shared__ int      counts[64];
    __shared__ int      offs[64];
    __shared__ float4   sv[32];
    __shared__ float4   sa[32];
    __shared__ float    sout[4][NUM_NEG];          // 16 KB output staging

    const int tid  = threadIdx.x;
    const int lane = tid & 31;
    const int w    = tid >> 5;                     // 8 warps
    const int c    = lane & 7;                     // float4-chunk within row
    const int r    = lane >> 3;                    // 8-lane group = row slot 0..3
    char* const wring = ring + (size_t)w * (D_ST * 2048);

    for (int rep = 0; rep < 2; ++rep) {
        const int b = blockIdx.x + rep * NBLK;     // 0..511

        // ---- build keys + zero counts ----
#pragma unroll
        for (int i = tid; i < NUM_NEG; i += 256) {
            const uint32_t row = (uint32_t)__ldg(neg_idx + (size_t)b * NUM_NEG + i);
            kbuf[i] = (row << 10) | (uint32_t)i;   // row<500000<2^19; j in 10 bits
        }
        if (tid < 64) counts[tid] = 0;
        __syncthreads();

        // ---- count pass; warps 0/1 also normalize v,a ----
#pragma unroll
        for (int i = tid; i < NUM_NEG; i += 256)
            atomicAdd(&counts[kbuf[i] >> 23], 1);  // bucket = row >> 13 (0..61)
        if (w == 0) {
            float4 x = reinterpret_cast<const float4*>(video)[b * 32 + lane];
            float ss = warp_sum(dot4(x, x));
            float inv = 1.0f / fmaxf(sqrtf(ss), 1e-12f);
            sv[lane] = make_float4(x.x * inv, x.y * inv, x.z * inv, x.w * inv);
        } else if (w == 1) {
            float4 x = reinterpret_cast<const float4*>(audio)[b * 32 + lane];
            float ss = warp_sum(dot4(x, x));
            float inv = 1.0f / fmaxf(sqrtf(ss), 1e-12f);
            sa[lane] = make_float4(x.x * inv, x.y * inv, x.z * inv, x.w * inv);
        }
        __syncthreads();

        // ---- exclusive scan of 64 counts (thread 0, trivial) ----
        if (tid == 0) {
            int acc = 0;
#pragma unroll
            for (int k = 0; k < 64; ++k) { offs[k] = acc; acc += counts[k]; }
        }
        __syncthreads();

        // ---- scatter into bucket order ----
#pragma unroll
        for (int i = tid; i < NUM_NEG; i += 256) {
            const uint32_t k2 = kbuf[i];
            const int p = atomicAdd(&offs[k2 >> 23], 1);
            sorted[p] = k2;
        }
        __syncthreads();                           // sorted + sv/sa ready

        const float4 v0 = sv[c], v1 = sv[c + 8], v2 = sv[c + 16], v3 = sv[c + 24];
        const float4 a0 = sa[c], a1 = sa[c + 8], a2 = sa[c + 16], a3 = sa[c + 24];

        // ---- prologue: issue stages 0..D_ST-2 ----
#pragma unroll
        for (int g = 0; g < D_ST - 1; ++g) {
#pragma unroll
            for (int i = 0; i < 4; ++i) {
                const int p  = g * 16 + w * 2 + (i >> 1);
                const int ni = (int)(sorted[p] >> 10);
                const float4* src = ((i & 1) ? m2 : m1) + (size_t)ni * 32 + lane;
                uint32_t dst = (uint32_t)__cvta_generic_to_shared(
                    wring + (g % D_ST) * 2048 + i * 512 + lane * 16);
                cp_async16(dst, src);
            }
            cp_commit();
        }

        // ---- pos + self dots for this b (direct LDG, overlaps fill) ----
        {
            const int j  = w * 4 + r;
            const int pi = __ldg(pos_idx + (size_t)b * POS_K + j);
            const float4* p1 = m1 + (size_t)pi * 32 + c;
            const float4* p2 = m2 + (size_t)pi * 32 + c;
            float dvv = dot4(p1[0], v0) + dot4(p1[8], v1) + dot4(p1[16], v2) + dot4(p1[24], v3);
            float daa = dot4(p2[0], a0) + dot4(p2[8], a1) + dot4(p2[16], a2) + dot4(p2[24], a3);
            grp8_sum2(dvv, daa);
            if (c == 0) {
                out[O4 + (size_t)b * POS_K + j] = dvv * INV_TEMP;
                out[O6 + (size_t)b * POS_K + j] = daa * INV_TEMP;
            }
            if (w == 0 && r < 2) {
                const int yi = __ldg(y + b);
                const float4* p = (r == 0 ? m1 : m2) + (size_t)yi * 32 + c;
                float d;
                if (r == 0) d = dot4(p[0], a0) + dot4(p[8], a1) + dot4(p[16], a2) + dot4(p[24], a3);
                else        d = dot4(p[0], v0) + dot4(p[8], v1) + dot4(p[16], v2) + dot4(p[24], v3);
#pragma unroll
                for (int o = 4; o; o >>= 1) d += __shfl_xor_sync(0x0000ffffu, d, o);
                if (c == 0) {
                    if (r == 0) out[O2 + b] = d * INV_TEMP;  // inst_a2v_pos
                    else        out[O0 + b] = d * INV_TEMP;  // inst_v2a_pos
                }
            }
        }

        // ---- sorted sweep: 64 stages, per-warp decoupled ----
        for (int s = 0; s < N_ST; ++s) {
            cp_wait<D_ST - 2>();                   // stage s landed for this warp
            __syncwarp();

            const int sn = s + D_ST - 1;
            if (sn < N_ST) {
#pragma unroll
                for (int i = 0; i < 4; ++i) {
                    const int p  = sn * 16 + w * 2 + (i >> 1);
                    const int ni = (int)(sorted[p] >> 10);
                    const float4* src = ((i & 1) ? m2 : m1) + (size_t)ni * 32 + lane;
                    uint32_t dst = (uint32_t)__cvta_generic_to_shared(
                        wring + (sn % D_ST) * 2048 + i * 512 + lane * 16);
                    cp_async16(dst, src);
                }
            }
            cp_commit();

            // compute: group r handles row slot r (neg r>>1, bank r&1)
            const float4* buf = reinterpret_cast<const float4*>(
                wring + (s % D_ST) * 2048) + (size_t)r * 32;
            const float4 x0 = buf[c], x1 = buf[c + 8], x2 = buf[c + 16], x3 = buf[c + 24];
            float dv = dot4(x0, v0) + dot4(x1, v1) + dot4(x2, v2) + dot4(x3, v3);
            float da = dot4(x0, a0) + dot4(x1, a1) + dot4(x2, a2) + dot4(x3, a3);
            grp8_sum2(dv, da);

            if (c == 0) {
                const int j = (int)(sorted[s * 16 + w * 2 + (r >> 1)] & 1023u);
                if ((r & 1) == 0) {                // m1 row: ·a -> O3, ·v -> O5
                    sout[1][j] = da * INV_TEMP;
                    sout[2][j] = dv * INV_TEMP;
                } else {                           // m2 row: ·v -> O1, ·a -> O7
                    sout[0][j] = dv * INV_TEMP;
                    sout[3][j] = da * INV_TEMP;
                }
            }
        }

        cp_wait<0>();
        __syncthreads();                           // sout complete, ring reusable

        // ---- coalesced output flush ----
#pragma unroll
        for (int i = tid; i < NUM_NEG; i += 256) {
            const size_t o = (size_t)b * NUM_NEG + i;
            out[O1 + o] = sout[0][i];
            out[O3 + o] = sout[1][i];
            out[O5 + o] = sout[2][i];
            out[O7 + o] = sout[3][i];
        }
        __syncthreads();                           // before rep1 overwrites smem
    }
}

extern "C" void kernel_launch(void* const* d_in, const int* in_sizes, int n_in,
                              void* d_out, int out_size)
{
    const float* video = (const float*)d_in[0];
    const float* audio = (const float*)d_in[1];
    const float4* m1   = (const float4*)d_in[2];
    const float4* m2   = (const float4*)d_in[3];
    const int* y       = (const int*)d_in[4];
    const int* pos_idx = (const int*)d_in[5];
    const int* neg_idx = (const int*)d_in[6];
    float* out         = (float*)d_out;

    const int dyn_smem = 8 * D_ST * 2048;   // 64 KB ring
    cudaFuncSetAttribute(avid_cma_kernel,
                         cudaFuncAttributeMaxDynamicSharedMemorySize, dyn_smem);

    avid_cma_kernel<<<NBLK, 256, dyn_smem>>>(video, audio, m1, m2, y,
                                             pos_idx, neg_idx, out);
}